// round 13
// baseline (speedup 1.0000x reference)
#include <cuda_runtime.h>
#include <cuda_bf16.h>
#include <cstdint>
#include <cstddef>

#define D_DIM  2048
#define NEXP   64
#define TILE_M 64
#define KC     32
#define NCH    (D_DIM / KC)   // 64 chunks
#define NTHR   128
#define MARGIN 4e-4f
#define MAXC   16

// ---- smem (41.2 KB/CTA so 4 CTAs/SM fit): 2-deep A + 2-deep B(hi|lo) + bias ----
// A: fp32, 64 rows x 160B stride (proven conflict-free frag pattern)
// B: bf16, 64 rows x 80B stride  (proven conflict-free)
#define A_OFF    0
#define STG      10240            // both A-stage (64*160) and B-stage (2*64*80)
#define B_OFF    20480
#define BIAS_OFF 40960
#define SMEM_TOTAL 41216
#define LG_PAD   66

__device__ __nv_bfloat16 g_Wh[NEXP * D_DIM];   // RN bf16 hi of W
__device__ __nv_bfloat16 g_Wm[NEXP * D_DIM];   // RN bf16 of residual

// ---------------- helpers ----------------
__device__ __forceinline__ uint32_t smem_u32(const void* p) {
    uint32_t a;
    asm("{ .reg .u64 t; cvta.to.shared.u64 t, %1; cvt.u32.u64 %0, t; }" : "=r"(a) : "l"(p));
    return a;
}
__device__ __forceinline__ void cpa16(void* dst, const void* src) {
    asm volatile("cp.async.cg.shared.global [%0], [%1], 16;"
                 :: "r"(smem_u32(dst)), "l"(src) : "memory");
}
#define CP_COMMIT() asm volatile("cp.async.commit_group;" ::: "memory")
#define CP_WAIT(n)  asm volatile("cp.async.wait_group %0;" :: "n"(n) : "memory")

__device__ __forceinline__ void mma_bf16(float* c, const uint32_t* a, uint32_t b0, uint32_t b1) {
    asm volatile("mma.sync.aligned.m16n8k16.row.col.f32.bf16.bf16.f32 "
        "{%0,%1,%2,%3}, {%4,%5,%6,%7}, {%8,%9}, {%0,%1,%2,%3};"
        : "+f"(c[0]), "+f"(c[1]), "+f"(c[2]), "+f"(c[3])
        : "r"(a[0]), "r"(a[1]), "r"(a[2]), "r"(a[3]), "r"(b0), "r"(b1));
}

// split k-adjacent float pair -> hi-bf16x2 (truncate) + lo-bf16x2 (RN of exact residual)
__device__ __forceinline__ void splitpair(float x, float y, uint32_t& hi, uint32_t& lo) {
    uint32_t xb = __float_as_uint(x), yb = __float_as_uint(y);
    hi = __byte_perm(xb, yb, 0x7632);
    float lx = x - __uint_as_float(xb & 0xFFFF0000u);
    float ly = y - __uint_as_float(yb & 0xFFFF0000u);
    asm("cvt.rn.bf16x2.f32 %0, %1, %2;" : "=r"(lo) : "f"(ly), "f"(lx));
}

// ---------------- W pre-split (RN 2-way) ----------------
__global__ void conv_w_kernel(const float* __restrict__ W) {
    int i = blockIdx.x * 256 + threadIdx.x;
    float x = W[i];
    __nv_bfloat16 h = __float2bfloat16(x);
    __nv_bfloat16 m = __float2bfloat16(x - __bfloat162float(h));
    g_Wh[i] = h; g_Wm[i] = m;
}

// ---------------- main fused kernel: 64-reg cap -> 4 CTAs/SM under 32K RF ----------------
__global__ __launch_bounds__(NTHR, 8)
void moe_gate_mma(const float* __restrict__ r, const float* __restrict__ W,
                  const float* __restrict__ bias,
                  float* __restrict__ out, size_t soft_base)
{
    extern __shared__ char smem[];
    const int tid  = threadIdx.x;
    const int warp = tid >> 5, lane = tid & 31;
    const int g    = lane >> 2, tg = lane & 3;
    const int row0 = blockIdx.x * TILE_M;

    if (tid < NEXP) *(float*)(smem + BIAS_OFF + tid * 4) = bias[tid];

    auto issue = [&](int ci) {
        const int s  = ci & 1;
        const int k0 = ci * KC;
#pragma unroll
        for (int i = 0; i < 4; i++) {                 // A: 64 rows x 8 x 16B
            int id = tid + i * NTHR;
            int row = id >> 3, seg = id & 7;
            cpa16(smem + A_OFF + s * STG + row * 160 + seg * 16,
                  r + (size_t)(row0 + row) * D_DIM + k0 + seg * 4);
        }
#pragma unroll
        for (int i = 0; i < 2; i++) {                 // B hi: 64 rows x 4 x 16B
            int id = tid + i * NTHR;
            int e = id >> 2, seg = id & 3;
            cpa16(smem + B_OFF + s * STG + e * 80 + seg * 16,
                  g_Wh + (size_t)e * D_DIM + k0 + seg * 8);
        }
#pragma unroll
        for (int i = 0; i < 2; i++) {                 // B lo
            int id = tid + i * NTHR;
            int e = id >> 2, seg = id & 3;
            cpa16(smem + B_OFF + s * STG + 5120 + e * 80 + seg * 16,
                  g_Wm + (size_t)e * D_DIM + k0 + seg * 8);
        }
        CP_COMMIT();
    };

    issue(0);
    issue(1);

    float c[8][4];
#pragma unroll
    for (int nt = 0; nt < 8; nt++)
#pragma unroll
        for (int j = 0; j < 4; j++) c[nt][j] = 0.f;

    for (int ci = 0; ci < NCH; ci++) {
        const int s = ci & 1;
        if (ci == NCH - 1) { CP_WAIT(0); } else { CP_WAIT(1); }
        __syncthreads();

        const char* As = smem + A_OFF + s * STG;
        const char* Bh = smem + B_OFF + s * STG;
        const char* Bl = Bh + 5120;

#pragma unroll
        for (int ks = 0; ks < 2; ks++) {              // k16 steps
            uint32_t ahi[4], alo[4];
            {
                const char* ap = As + (warp * 16 + g) * 160 + ks * 64 + tg * 8;
                float2 x0 = *(const float2*)ap;
                float2 x2 = *(const float2*)(ap + 32);
                float2 x1 = *(const float2*)(ap + 8 * 160);
                float2 x3 = *(const float2*)(ap + 8 * 160 + 32);
                splitpair(x0.x, x0.y, ahi[0], alo[0]);
                splitpair(x1.x, x1.y, ahi[1], alo[1]);
                splitpair(x2.x, x2.y, ahi[2], alo[2]);
                splitpair(x3.x, x3.y, ahi[3], alo[3]);
            }
#pragma unroll
            for (int nt = 0; nt < 8; nt++) {
                const char* pb = Bh + (nt * 8 + g) * 80 + ks * 32 + tg * 4;
                uint32_t bh0 = *(const uint32_t*)pb;
                uint32_t bh1 = *(const uint32_t*)(pb + 16);
                const char* pl = Bl + (nt * 8 + g) * 80 + ks * 32 + tg * 4;
                uint32_t bl0 = *(const uint32_t*)pl;
                uint32_t bl1 = *(const uint32_t*)(pl + 16);
                mma_bf16(c[nt], ahi, bh0, bh1);   // hi*hi
                mma_bf16(c[nt], ahi, bl0, bl1);   // hi*lo
                mma_bf16(c[nt], alo, bh0, bh1);   // lo*hi
            }
        }
        __syncthreads();                   // all warps done with stage s
        if (ci + 2 < NCH) issue(ci + 2);   // refill it
    }
    __syncthreads();

    // ---- scatter C frags (+bias) to logits[64][LG_PAD] in smem
    float* lg = (float*)smem;
    const float* bs = (const float*)(smem + BIAS_OFF);
#pragma unroll
    for (int nt = 0; nt < 8; nt++) {
        int rr = warp * 16 + g, cc = nt * 8 + tg * 2;
        lg[rr * LG_PAD + cc]           = c[nt][0] + bs[cc];
        lg[rr * LG_PAD + cc + 1]       = c[nt][1] + bs[cc + 1];
        lg[(rr + 8) * LG_PAD + cc]     = c[nt][2] + bs[cc];
        lg[(rr + 8) * LG_PAD + cc + 1] = c[nt][3] + bs[cc + 1];
    }
    __syncthreads();

    // ---- epilogue: stream logits from smem (no 64-reg array -> fits 64-reg cap)
    if (tid < TILE_M) {
        const int myrow = row0 + tid;
        const float* lrow = lg + tid * LG_PAD;

        float mx = -3.4e38f;
#pragma unroll
        for (int cc = 0; cc < NEXP; cc++) mx = fmaxf(mx, lrow[cc]);
        float ssum = 0.f;
#pragma unroll
        for (int cc = 0; cc < NEXP; cc++) ssum += __expf(lrow[cc] - mx);

        float t[9];
#pragma unroll
        for (int j = 0; j < 9; j++) t[j] = -3.4e38f;
        for (int cc = 0; cc < NEXP; cc++) {
            float x = lrow[cc];
#pragma unroll
            for (int j = 0; j < 9; j++) {
                float hi = fmaxf(t[j], x), lo = fminf(t[j], x);
                t[j] = hi; x = lo;
            }
        }
        float thr = t[7];
        unsigned long long msk = 0ull;

        if (thr - t[8] >= MARGIN) {
            int cnt_gt = 0;
            for (int cc = 0; cc < NEXP; cc++) cnt_gt += (lrow[cc] > thr) ? 1 : 0;
            int quota = 8 - cnt_gt, eq = 0;
            for (int cc = 0; cc < NEXP; cc++) {
                float x = lrow[cc];
                bool sg = x > thr;
                bool se = (x == thr) && (eq < quota);
                if (se) eq++;
                if (sg || se) msk |= 1ull << cc;
            }
        } else {
            // ambiguous boundary (~1% rows): exact fp32 recompute of candidates
            int   cidx[MAXC];
            float cval[MAXC];
            int nc = 0;
            float lim = thr - MARGIN;
            for (int cc = 0; cc < NEXP; cc++)
                if (lrow[cc] >= lim && nc < MAXC) { cidx[nc++] = cc; }

            const float* rrow = r + (size_t)myrow * D_DIM;
            for (int j = 0; j < nc; j++) {
                const float* wrow = W + (size_t)cidx[j] * D_DIM;
                float s0 = 0.f, s1 = 0.f, s2 = 0.f, s3 = 0.f;
                for (int k = 0; k < D_DIM; k += 4) {
                    float4 a = *(const float4*)(rrow + k);
                    float4 w = *(const float4*)(wrow + k);
                    s0 = fmaf(a.x, w.x, s0); s1 = fmaf(a.y, w.y, s1);
                    s2 = fmaf(a.z, w.z, s2); s3 = fmaf(a.w, w.w, s3);
                }
                cval[j] = (s0 + s1) + (s2 + s3) + bs[cidx[j]];
            }
            for (int it = 0; it < 8; it++) {
                float best = -3.4e38f; int bj = 0;
                for (int j = 0; j < nc; j++) {
                    bool freej = ((msk >> cidx[j]) & 1ull) == 0ull;
                    if (freej && cval[j] > best) { best = cval[j]; bj = j; }
                }
                msk |= 1ull << cidx[bj];
            }
        }

        float selexp = 0.f;
        for (int cc = 0; cc < NEXP; cc++)
            if ((msk >> cc) & 1ull) selexp += __expf(lrow[cc] - mx);

        float inv_s = 1.0f / ssum;
        float inv_d = 1.0f / (selexp * inv_s + 1e-9f);

        const size_t gr = (size_t)myrow * NEXP;
#pragma unroll
        for (int c4 = 0; c4 < NEXP; c4 += 4) {
            float sf[4], hd[4];
#pragma unroll
            for (int j = 0; j < 4; j++) {
                float soft = __expf(lrow[c4 + j] - mx) * inv_s;
                sf[j] = soft;
                hd[j] = ((msk >> (c4 + j)) & 1ull) ? soft * inv_d : 0.f;
            }
            *(float4*)(out + gr + c4)             = make_float4(hd[0], hd[1], hd[2], hd[3]);
            *(float4*)(out + soft_base + gr + c4) = make_float4(sf[0], sf[1], sf[2], sf[3]);
        }
    }
}

extern "C" void kernel_launch(void* const* d_in, const int* in_sizes, int n_in,
                              void* d_out, int out_size)
{
    const float* r = (const float*)d_in[0];   // (B, 2048) fp32
    const float* W = (const float*)d_in[1];   // (64, 2048) fp32
    const float* b = (const float*)d_in[2];   // (64,) fp32
    float* out = (float*)d_out;               // [hard | soft]

    int B = in_sizes[0] / D_DIM;              // 32768
    size_t soft_base = (size_t)out_size / 2;

    cudaFuncSetAttribute(moe_gate_mma, cudaFuncAttributeMaxDynamicSharedMemorySize, SMEM_TOTAL);
    cudaFuncSetAttribute(moe_gate_mma, cudaFuncAttributePreferredSharedMemoryCarveout, 100);

    conv_w_kernel<<<(NEXP * D_DIM) / 256, 256>>>(W);
    moe_gate_mma<<<B / TILE_M, NTHR, SMEM_TOTAL>>>(r, W, b, out, soft_base);
}

// round 14
// speedup vs baseline: 1.5690x; 1.5690x over previous
#include <cuda_runtime.h>
#include <cuda_bf16.h>
#include <cstdint>
#include <cstddef>

#define D_DIM  2048
#define NEXP   64
#define TILE_M 256
#define KC     32
#define NCH    (D_DIM / KC)   // 64 chunks
#define NTHR   512
#define MARGIN 4e-4f
#define MAXC   16

// ---- smem: 4 stages of [A 256x160B | Bh 64x80B | Bl 64x80B] + bias ----
#define A_SZ     40960            // 256 * 160
#define B_SZ     5120             // 64 * 80
#define STG      51200            // A_SZ + 2*B_SZ
#define NSTG     4
#define BIAS_OFF 204800
#define SMEM_TOTAL 205056
#define LG_PAD   66               // logits 256*66*4 = 67.6KB, reuses stage area

__device__ __nv_bfloat16 g_Wh[NEXP * D_DIM];   // RN bf16 hi of W
__device__ __nv_bfloat16 g_Wm[NEXP * D_DIM];   // RN bf16 of residual

// ---------------- helpers ----------------
__device__ __forceinline__ uint32_t smem_u32(const void* p) {
    uint32_t a;
    asm("{ .reg .u64 t; cvta.to.shared.u64 t, %1; cvt.u32.u64 %0, t; }" : "=r"(a) : "l"(p));
    return a;
}
__device__ __forceinline__ void cpa16(void* dst, const void* src) {
    asm volatile("cp.async.cg.shared.global [%0], [%1], 16;"
                 :: "r"(smem_u32(dst)), "l"(src) : "memory");
}
#define CP_COMMIT() asm volatile("cp.async.commit_group;" ::: "memory")
#define CP_WAIT(n)  asm volatile("cp.async.wait_group %0;" :: "n"(n) : "memory")

__device__ __forceinline__ void mma_bf16(float* c, const uint32_t* a, uint32_t b0, uint32_t b1) {
    asm volatile("mma.sync.aligned.m16n8k16.row.col.f32.bf16.bf16.f32 "
        "{%0,%1,%2,%3}, {%4,%5,%6,%7}, {%8,%9}, {%0,%1,%2,%3};"
        : "+f"(c[0]), "+f"(c[1]), "+f"(c[2]), "+f"(c[3])
        : "r"(a[0]), "r"(a[1]), "r"(a[2]), "r"(a[3]), "r"(b0), "r"(b1));
}

// split k-adjacent float pair -> hi-bf16x2 (truncate) + lo-bf16x2 (RN of exact residual)
__device__ __forceinline__ void splitpair(float x, float y, uint32_t& hi, uint32_t& lo) {
    uint32_t xb = __float_as_uint(x), yb = __float_as_uint(y);
    hi = __byte_perm(xb, yb, 0x7632);
    float lx = x - __uint_as_float(xb & 0xFFFF0000u);
    float ly = y - __uint_as_float(yb & 0xFFFF0000u);
    asm("cvt.rn.bf16x2.f32 %0, %1, %2;" : "=r"(lo) : "f"(ly), "f"(lx));
}

// ---------------- W pre-split (RN 2-way) ----------------
__global__ void conv_w_kernel(const float* __restrict__ W) {
    int i = blockIdx.x * 256 + threadIdx.x;
    float x = W[i];
    __nv_bfloat16 h = __float2bfloat16(x);
    __nv_bfloat16 m = __float2bfloat16(x - __bfloat162float(h));
    g_Wh[i] = h; g_Wm[i] = m;
}

// ---------------- main fused kernel: 1 wave of 128 big CTAs ----------------
__global__ __launch_bounds__(NTHR, 1)
void moe_gate_mma(const float* __restrict__ r, const float* __restrict__ W,
                  const float* __restrict__ bias,
                  float* __restrict__ out, size_t soft_base)
{
    extern __shared__ char smem[];
    const int tid  = threadIdx.x;
    const int warp = tid >> 5, lane = tid & 31;
    const int g    = lane >> 2, tg = lane & 3;
    const int wm   = warp & 7, wn = warp >> 3;     // 8 M-warps x 2 N-warps
    const int row0 = blockIdx.x * TILE_M;

    if (tid < NEXP) *(float*)(smem + BIAS_OFF + tid * 4) = bias[tid];

    auto issue = [&](int ci) {
        char* base = smem + (ci & 3) * STG;
        const int k0 = ci * KC;
#pragma unroll
        for (int i = 0; i < 4; i++) {                 // A: 256 rows x 8 x 16B
            int id = tid + i * NTHR;
            int row = id >> 3, seg = id & 7;
            cpa16(base + row * 160 + seg * 16,
                  r + (size_t)(row0 + row) * D_DIM + k0 + seg * 4);
        }
        {                                             // B hi (tid<256) / lo (tid>=256)
            int t2 = tid & 255;
            int e = t2 >> 2, seg = t2 & 3;
            const __nv_bfloat16* src = (tid < 256 ? g_Wh : g_Wm) + (size_t)e * D_DIM + k0 + seg * 8;
            char* dst = base + A_SZ + (tid < 256 ? 0 : B_SZ) + e * 80 + seg * 16;
            cpa16(dst, src);
        }
        CP_COMMIT();
    };

    issue(0); issue(1); issue(2);

    float c[2][4][4];
#pragma unroll
    for (int mt = 0; mt < 2; mt++)
#pragma unroll
        for (int nt = 0; nt < 4; nt++)
#pragma unroll
            for (int j = 0; j < 4; j++) c[mt][nt][j] = 0.f;

    for (int ci = 0; ci < NCH; ci++) {
        if (ci <= NCH - 3)      { CP_WAIT(2); }
        else if (ci == NCH - 2) { CP_WAIT(1); }
        else                    { CP_WAIT(0); }
        __syncthreads();
        // refill stage (ci+3)&3 == (ci-1)&3 — consumed last iteration, race-free
        if (ci + 3 < NCH) issue(ci + 3);

        const char* As = smem + (ci & 3) * STG;
        const char* Bh = As + A_SZ;
        const char* Bl = Bh + B_SZ;

#pragma unroll
        for (int ks = 0; ks < 2; ks++) {
            uint32_t ahi[2][4], alo[2][4];
#pragma unroll
            for (int mt = 0; mt < 2; mt++) {
                const char* ap = As + (wm * 32 + mt * 16 + g) * 160 + ks * 64 + tg * 8;
                float2 x0 = *(const float2*)ap;
                float2 x2 = *(const float2*)(ap + 32);
                float2 x1 = *(const float2*)(ap + 8 * 160);
                float2 x3 = *(const float2*)(ap + 8 * 160 + 32);
                splitpair(x0.x, x0.y, ahi[mt][0], alo[mt][0]);
                splitpair(x1.x, x1.y, ahi[mt][1], alo[mt][1]);
                splitpair(x2.x, x2.y, ahi[mt][2], alo[mt][2]);
                splitpair(x3.x, x3.y, ahi[mt][3], alo[mt][3]);
            }
#pragma unroll
            for (int nt = 0; nt < 4; nt++) {
                const char* pb = Bh + (wn * 32 + nt * 8 + g) * 80 + ks * 32 + tg * 4;
                uint32_t bh0 = *(const uint32_t*)pb;
                uint32_t bh1 = *(const uint32_t*)(pb + 16);
                const char* pl = Bl + (wn * 32 + nt * 8 + g) * 80 + ks * 32 + tg * 4;
                uint32_t bl0 = *(const uint32_t*)pl;
                uint32_t bl1 = *(const uint32_t*)(pl + 16);
#pragma unroll
                for (int mt = 0; mt < 2; mt++) {
                    mma_bf16(c[mt][nt], ahi[mt], bh0, bh1);   // hi*hi
                    mma_bf16(c[mt][nt], ahi[mt], bl0, bl1);   // hi*lo
                    mma_bf16(c[mt][nt], alo[mt], bh0, bh1);   // lo*hi
                }
            }
        }
    }
    __syncthreads();

    // ---- scatter C frags (+bias) to logits[256][LG_PAD]
    float* lg = (float*)smem;
    const float* bs = (const float*)(smem + BIAS_OFF);
#pragma unroll
    for (int mt = 0; mt < 2; mt++)
#pragma unroll
        for (int nt = 0; nt < 4; nt++) {
            int rr = wm * 32 + mt * 16 + g, cc = wn * 32 + nt * 8 + tg * 2;
            lg[rr * LG_PAD + cc]           = c[mt][nt][0] + bs[cc];
            lg[rr * LG_PAD + cc + 1]       = c[mt][nt][1] + bs[cc + 1];
            lg[(rr + 8) * LG_PAD + cc]     = c[mt][nt][2] + bs[cc];
            lg[(rr + 8) * LG_PAD + cc + 1] = c[mt][nt][3] + bs[cc + 1];
        }
    __syncthreads();

    // ---- epilogue: one thread per row, streaming logits from smem
    if (tid < TILE_M) {
        const int myrow = row0 + tid;
        const float* lrow = lg + tid * LG_PAD;

        float mx = -3.4e38f;
#pragma unroll
        for (int cc = 0; cc < NEXP; cc++) mx = fmaxf(mx, lrow[cc]);
        float ssum = 0.f;
#pragma unroll
        for (int cc = 0; cc < NEXP; cc++) ssum += __expf(lrow[cc] - mx);

        float t[9];
#pragma unroll
        for (int j = 0; j < 9; j++) t[j] = -3.4e38f;
        for (int cc = 0; cc < NEXP; cc++) {
            float x = lrow[cc];
#pragma unroll
            for (int j = 0; j < 9; j++) {
                float hi = fmaxf(t[j], x), lo = fminf(t[j], x);
                t[j] = hi; x = lo;
            }
        }
        float thr = t[7];
        unsigned long long msk = 0ull;

        if (thr - t[8] >= MARGIN) {
            int cnt_gt = 0;
            for (int cc = 0; cc < NEXP; cc++) cnt_gt += (lrow[cc] > thr) ? 1 : 0;
            int quota = 8 - cnt_gt, eq = 0;
            for (int cc = 0; cc < NEXP; cc++) {
                float x = lrow[cc];
                bool sg = x > thr;
                bool se = (x == thr) && (eq < quota);
                if (se) eq++;
                if (sg || se) msk |= 1ull << cc;
            }
        } else {
            // ambiguous boundary (~1% rows): exact fp32 recompute of candidates
            int   cidx[MAXC];
            float cval[MAXC];
            int nc = 0;
            float lim = thr - MARGIN;
            for (int cc = 0; cc < NEXP; cc++)
                if (lrow[cc] >= lim && nc < MAXC) { cidx[nc++] = cc; }

            const float* rrow = r + (size_t)myrow * D_DIM;
            for (int j = 0; j < nc; j++) {
                const float* wrow = W + (size_t)cidx[j] * D_DIM;
                float s0 = 0.f, s1 = 0.f, s2 = 0.f, s3 = 0.f;
                for (int k = 0; k < D_DIM; k += 4) {
                    float4 a = *(const float4*)(rrow + k);
                    float4 w = *(const float4*)(wrow + k);
                    s0 = fmaf(a.x, w.x, s0); s1 = fmaf(a.y, w.y, s1);
                    s2 = fmaf(a.z, w.z, s2); s3 = fmaf(a.w, w.w, s3);
                }
                cval[j] = (s0 + s1) + (s2 + s3) + bs[cidx[j]];
            }
            for (int it = 0; it < 8; it++) {
                float best = -3.4e38f; int bj = 0;
                for (int j = 0; j < nc; j++) {
                    bool freej = ((msk >> cidx[j]) & 1ull) == 0ull;
                    if (freej && cval[j] > best) { best = cval[j]; bj = j; }
                }
                msk |= 1ull << cidx[bj];
            }
        }

        float selexp = 0.f;
        for (int cc = 0; cc < NEXP; cc++)
            if ((msk >> cc) & 1ull) selexp += __expf(lrow[cc] - mx);

        float inv_s = 1.0f / ssum;
        float inv_d = 1.0f / (selexp * inv_s + 1e-9f);

        const size_t gr = (size_t)myrow * NEXP;
#pragma unroll
        for (int c4 = 0; c4 < NEXP; c4 += 4) {
            float sf[4], hd[4];
#pragma unroll
            for (int j = 0; j < 4; j++) {
                float soft = __expf(lrow[c4 + j] - mx) * inv_s;
                sf[j] = soft;
                hd[j] = ((msk >> (c4 + j)) & 1ull) ? soft * inv_d : 0.f;
            }
            *(float4*)(out + gr + c4)             = make_float4(hd[0], hd[1], hd[2], hd[3]);
            *(float4*)(out + soft_base + gr + c4) = make_float4(sf[0], sf[1], sf[2], sf[3]);
        }
    }
}

extern "C" void kernel_launch(void* const* d_in, const int* in_sizes, int n_in,
                              void* d_out, int out_size)
{
    const float* r = (const float*)d_in[0];   // (B, 2048) fp32
    const float* W = (const float*)d_in[1];   // (64, 2048) fp32
    const float* b = (const float*)d_in[2];   // (64,) fp32
    float* out = (float*)d_out;               // [hard | soft]

    int B = in_sizes[0] / D_DIM;              // 32768
    size_t soft_base = (size_t)out_size / 2;

    cudaFuncSetAttribute(moe_gate_mma, cudaFuncAttributeMaxDynamicSharedMemorySize, SMEM_TOTAL);

    conv_w_kernel<<<(NEXP * D_DIM) / 256, 256>>>(W);
    moe_gate_mma<<<B / TILE_M, NTHR, SMEM_TOTAL>>>(r, W, b, out, soft_base);
}

// round 15
// speedup vs baseline: 2.3576x; 1.5026x over previous
#include <cuda_runtime.h>
#include <cuda_bf16.h>
#include <cstdint>
#include <cstddef>

#define D_DIM  2048
#define NEXP   64
#define TILE_M 128
#define KC     64
#define NCH    (D_DIM / KC)   // 32 chunks
#define NTHR   256
#define MARGIN 4e-4f
#define MAXC   16

// ---- smem: 4 B-stages [hi 64x144B | lo 64x144B] + bias; A never touches smem ----
#define BSTG     18432            // 2 * 64 * 144
#define BIAS_OFF 73728            // 4 * BSTG
#define SMEM_TOTAL 73984
#define LG_PAD   66               // logits 128*66*4 = 33.8KB, reuses stage area

__device__ __nv_bfloat16 g_Wh[NEXP * D_DIM];   // RN bf16 hi of W
__device__ __nv_bfloat16 g_Wm[NEXP * D_DIM];   // RN bf16 of residual

// ---------------- helpers ----------------
__device__ __forceinline__ uint32_t smem_u32(const void* p) {
    uint32_t a;
    asm("{ .reg .u64 t; cvta.to.shared.u64 t, %1; cvt.u32.u64 %0, t; }" : "=r"(a) : "l"(p));
    return a;
}
__device__ __forceinline__ void cpa16(void* dst, const void* src) {
    asm volatile("cp.async.cg.shared.global [%0], [%1], 16;"
                 :: "r"(smem_u32(dst)), "l"(src) : "memory");
}
#define CP_COMMIT() asm volatile("cp.async.commit_group;" ::: "memory")
#define CP_WAIT(n)  asm volatile("cp.async.wait_group %0;" :: "n"(n) : "memory")

__device__ __forceinline__ void mma_bf16(float* c, const uint32_t* a, uint32_t b0, uint32_t b1) {
    asm volatile("mma.sync.aligned.m16n8k16.row.col.f32.bf16.bf16.f32 "
        "{%0,%1,%2,%3}, {%4,%5,%6,%7}, {%8,%9}, {%0,%1,%2,%3};"
        : "+f"(c[0]), "+f"(c[1]), "+f"(c[2]), "+f"(c[3])
        : "r"(a[0]), "r"(a[1]), "r"(a[2]), "r"(a[3]), "r"(b0), "r"(b1));
}

// split k-adjacent float pair -> hi-bf16x2 (truncate) + lo-bf16x2 (RN of exact residual)
__device__ __forceinline__ void splitpair(float x, float y, uint32_t& hi, uint32_t& lo) {
    uint32_t xb = __float_as_uint(x), yb = __float_as_uint(y);
    hi = __byte_perm(xb, yb, 0x7632);
    float lx = x - __uint_as_float(xb & 0xFFFF0000u);
    float ly = y - __uint_as_float(yb & 0xFFFF0000u);
    asm("cvt.rn.bf16x2.f32 %0, %1, %2;" : "=r"(lo) : "f"(ly), "f"(lx));
}

// ---------------- W pre-split (RN 2-way) ----------------
__global__ void conv_w_kernel(const float* __restrict__ W) {
    int i = blockIdx.x * 256 + threadIdx.x;
    float x = W[i];
    __nv_bfloat16 h = __float2bfloat16(x);
    __nv_bfloat16 m = __float2bfloat16(x - __bfloat162float(h));
    g_Wh[i] = h; g_Wm[i] = m;
}

// ---------------- main fused kernel ----------------
__global__ __launch_bounds__(NTHR)
void moe_gate_mma(const float* __restrict__ r, const float* __restrict__ W,
                  const float* __restrict__ bias,
                  float* __restrict__ out, size_t soft_base)
{
    extern __shared__ char smem[];
    const int tid  = threadIdx.x;
    const int warp = tid >> 5, lane = tid & 31;
    const int g    = lane >> 2, tg = lane & 3;
    const int row0 = blockIdx.x * TILE_M;

    if (tid < NEXP) *(float*)(smem + BIAS_OFF + tid * 4) = bias[tid];

    // B stage loader: 64 experts x 64 k (hi + lo), 144B row stride
    auto issueB = [&](int ci) {
        char* base = smem + (ci & 3) * BSTG;
        const int k0 = ci * KC;
#pragma unroll
        for (int i = 0; i < 2; i++) {
            int id = tid + i * NTHR;
            int e = id >> 3, seg = id & 7;
            cpa16(base + e * 144 + seg * 16,
                  g_Wh + (size_t)e * D_DIM + k0 + seg * 8);
        }
#pragma unroll
        for (int i = 0; i < 2; i++) {
            int id = tid + i * NTHR;
            int e = id >> 3, seg = id & 7;
            cpa16(base + 9216 + e * 144 + seg * 16,
                  g_Wm + (size_t)e * D_DIM + k0 + seg * 8);
        }
        CP_COMMIT();
    };

    // A: register-direct LDG, 16 outstanding LDG.64/thread for the next chunk
    const float* pa  = r + (size_t)(row0 + warp * 16 + g) * D_DIM + 2 * tg;
    const float* pa8 = pa + 8 * D_DIM;

    auto loadA = [&](int ci, float2* ab) {
        const int k0 = ci * KC;
#pragma unroll
        for (int i = 0; i < 8; i++) ab[i]     = *(const float2*)(pa  + k0 + 8 * i);
#pragma unroll
        for (int i = 0; i < 8; i++) ab[8 + i] = *(const float2*)(pa8 + k0 + 8 * i);
    };

    float c[8][4];
#pragma unroll
    for (int nt = 0; nt < 8; nt++)
#pragma unroll
        for (int j = 0; j < 4; j++) c[nt][j] = 0.f;

    auto mmaChunk = [&](int ci, const float2* ab) {
        const char* base = smem + (ci & 3) * BSTG;
#pragma unroll
        for (int ks = 0; ks < 4; ks++) {
            uint32_t ahi[4], alo[4];
            const int i = 2 * ks;
            splitpair(ab[i].x,     ab[i].y,     ahi[0], alo[0]);   // row g,   k lo
            splitpair(ab[8 + i].x, ab[8 + i].y, ahi[1], alo[1]);   // row g+8, k lo
            splitpair(ab[i + 1].x,     ab[i + 1].y,     ahi[2], alo[2]);   // row g,   k+8
            splitpair(ab[8 + i + 1].x, ab[8 + i + 1].y, ahi[3], alo[3]);   // row g+8, k+8
#pragma unroll
            for (int nt = 0; nt < 8; nt++) {
                const char* pb = base + (nt * 8 + g) * 144 + ks * 32 + tg * 4;
                uint32_t bh0 = *(const uint32_t*)pb;
                uint32_t bh1 = *(const uint32_t*)(pb + 16);
                const char* pl = pb + 9216;
                uint32_t bl0 = *(const uint32_t*)pl;
                uint32_t bl1 = *(const uint32_t*)(pl + 16);
                mma_bf16(c[nt], ahi, bh0, bh1);   // hi*hi
                mma_bf16(c[nt], ahi, bl0, bl1);   // hi*lo
                mma_bf16(c[nt], alo, bh0, bh1);   // lo*hi
            }
        }
    };

    // ---- prologue: 3 B stages committed, A chunk 0 in registers
    issueB(0); issueB(1); issueB(2);
    float2 abA[16], abB[16];
    loadA(0, abA);

    // ---- main loop, unrolled by 2 for A ping-pong (NCH = 32, even)
    for (int ci = 0; ci < NCH; ci += 2) {
        // chunk ci
        if (ci <= NCH - 3)      { CP_WAIT(2); }
        else if (ci == NCH - 2) { CP_WAIT(1); }
        else                    { CP_WAIT(0); }
        __syncthreads();
        if (ci + 3 < NCH) issueB(ci + 3);     // stage (ci-1)&3, consumed, race-free
        loadA(ci + 1, abB);                   // next A flies under current MMA
        mmaChunk(ci, abA);

        // chunk ci+1
        if (ci + 1 <= NCH - 3)      { CP_WAIT(2); }
        else if (ci + 1 == NCH - 2) { CP_WAIT(1); }
        else                        { CP_WAIT(0); }
        __syncthreads();
        if (ci + 4 < NCH) issueB(ci + 4);
        if (ci + 2 < NCH) loadA(ci + 2, abA);
        mmaChunk(ci + 1, abB);
    }
    __syncthreads();   // stage area free for logits staging

    // ---- scatter C frags (+bias) to logits[128][LG_PAD]
    float* lg = (float*)smem;
    const float* bs = (const float*)(smem + BIAS_OFF);
#pragma unroll
    for (int nt = 0; nt < 8; nt++) {
        int rr = warp * 16 + g, cc = nt * 8 + tg * 2;
        lg[rr * LG_PAD + cc]           = c[nt][0] + bs[cc];
        lg[rr * LG_PAD + cc + 1]       = c[nt][1] + bs[cc + 1];
        lg[(rr + 8) * LG_PAD + cc]     = c[nt][2] + bs[cc];
        lg[(rr + 8) * LG_PAD + cc + 1] = c[nt][3] + bs[cc + 1];
    }
    __syncthreads();

    // ---- epilogue: one thread per row, streaming from smem
    if (tid < TILE_M) {
        const int myrow = row0 + tid;
        const float* lrow = lg + tid * LG_PAD;

        float mx = -3.4e38f;
#pragma unroll
        for (int cc = 0; cc < NEXP; cc++) mx = fmaxf(mx, lrow[cc]);
        float ssum = 0.f;
#pragma unroll
        for (int cc = 0; cc < NEXP; cc++) ssum += __expf(lrow[cc] - mx);

        float t[9];
#pragma unroll
        for (int j = 0; j < 9; j++) t[j] = -3.4e38f;
        for (int cc = 0; cc < NEXP; cc++) {
            float x = lrow[cc];
#pragma unroll
            for (int j = 0; j < 9; j++) {
                float hi = fmaxf(t[j], x), lo = fminf(t[j], x);
                t[j] = hi; x = lo;
            }
        }
        float thr = t[7];
        unsigned long long msk = 0ull;

        if (thr - t[8] >= MARGIN) {
            int cnt_gt = 0;
            for (int cc = 0; cc < NEXP; cc++) cnt_gt += (lrow[cc] > thr) ? 1 : 0;
            int quota = 8 - cnt_gt, eq = 0;
            for (int cc = 0; cc < NEXP; cc++) {
                float x = lrow[cc];
                bool sg = x > thr;
                bool se = (x == thr) && (eq < quota);
                if (se) eq++;
                if (sg || se) msk |= 1ull << cc;
            }
        } else {
            // ambiguous boundary (~1% rows): exact fp32 recompute of candidates
            int   cidx[MAXC];
            float cval[MAXC];
            int nc = 0;
            float lim = thr - MARGIN;
            for (int cc = 0; cc < NEXP; cc++)
                if (lrow[cc] >= lim && nc < MAXC) { cidx[nc++] = cc; }

            const float* rrow = r + (size_t)myrow * D_DIM;
            for (int j = 0; j < nc; j++) {
                const float* wrow = W + (size_t)cidx[j] * D_DIM;
                float s0 = 0.f, s1 = 0.f, s2 = 0.f, s3 = 0.f;
                for (int k = 0; k < D_DIM; k += 4) {
                    float4 a = *(const float4*)(rrow + k);
                    float4 w = *(const float4*)(wrow + k);
                    s0 = fmaf(a.x, w.x, s0); s1 = fmaf(a.y, w.y, s1);
                    s2 = fmaf(a.z, w.z, s2); s3 = fmaf(a.w, w.w, s3);
                }
                cval[j] = (s0 + s1) + (s2 + s3) + bs[cidx[j]];
            }
            for (int it = 0; it < 8; it++) {
                float best = -3.4e38f; int bj = 0;
                for (int j = 0; j < nc; j++) {
                    bool freej = ((msk >> cidx[j]) & 1ull) == 0ull;
                    if (freej && cval[j] > best) { best = cval[j]; bj = j; }
                }
                msk |= 1ull << cidx[bj];
            }
        }

        float selexp = 0.f;
        for (int cc = 0; cc < NEXP; cc++)
            if ((msk >> cc) & 1ull) selexp += __expf(lrow[cc] - mx);

        float inv_s = 1.0f / ssum;
        float inv_d = 1.0f / (selexp * inv_s + 1e-9f);

        const size_t gr = (size_t)myrow * NEXP;
#pragma unroll
        for (int c4 = 0; c4 < NEXP; c4 += 4) {
            float sf[4], hd[4];
#pragma unroll
            for (int j = 0; j < 4; j++) {
                float soft = __expf(lrow[c4 + j] - mx) * inv_s;
                sf[j] = soft;
                hd[j] = ((msk >> (c4 + j)) & 1ull) ? soft * inv_d : 0.f;
            }
            *(float4*)(out + gr + c4)             = make_float4(hd[0], hd[1], hd[2], hd[3]);
            *(float4*)(out + soft_base + gr + c4) = make_float4(sf[0], sf[1], sf[2], sf[3]);
        }
    }
}

extern "C" void kernel_launch(void* const* d_in, const int* in_sizes, int n_in,
                              void* d_out, int out_size)
{
    const float* r = (const float*)d_in[0];   // (B, 2048) fp32
    const float* W = (const float*)d_in[1];   // (64, 2048) fp32
    const float* b = (const float*)d_in[2];   // (64,) fp32
    float* out = (float*)d_out;               // [hard | soft]

    int B = in_sizes[0] / D_DIM;              // 32768
    size_t soft_base = (size_t)out_size / 2;

    cudaFuncSetAttribute(moe_gate_mma, cudaFuncAttributeMaxDynamicSharedMemorySize, SMEM_TOTAL);

    conv_w_kernel<<<(NEXP * D_DIM) / 256, 256>>>(W);
    moe_gate_mma<<<B / TILE_M, NTHR, SMEM_TOTAL>>>(r, W, b, out, soft_base);
}

// round 16
// speedup vs baseline: 2.5370x; 1.0761x over previous
#include <cuda_runtime.h>
#include <cstdint>
#include <cstddef>

#define D_DIM  2048
#define NEXP   64
#define TILE_M 128
#define KC     32
#define NCH    (D_DIM / KC)   // 64 chunks
#define NTHR   128
#define MARGIN 2e-4f
#define MAXC   16

// ---- smem layout (bytes). Row stride 144B = 36 floats -> conflict-free frags.
#define A_OFF    0             // 3 stages x 128 rows x 144B
#define A_STG    18432
#define BH_OFF   55296         // 3 stages x 64 rows x 144B
#define B_STG    9216
#define BL_OFF   82944
#define BIAS_OFF 110592
#define SMEM_TOTAL 110848
#define LG_PAD   66            // epilogue logits row pad (floats)

__device__ float g_Whf[NEXP * D_DIM];   // tf32-valued hi part of W
__device__ float g_Wlf[NEXP * D_DIM];   // tf32-valued lo part of W

// ---------------- helpers ----------------
__device__ __forceinline__ uint32_t smem_u32(const void* p) {
    uint32_t a;
    asm("{ .reg .u64 t; cvta.to.shared.u64 t, %1; cvt.u32.u64 %0, t; }" : "=r"(a) : "l"(p));
    return a;
}
__device__ __forceinline__ void cpa16(void* dst, const void* src) {
    asm volatile("cp.async.cg.shared.global [%0], [%1], 16;"
                 :: "r"(smem_u32(dst)), "l"(src) : "memory");
}
#define CP_COMMIT() asm volatile("cp.async.commit_group;" ::: "memory")
#define CP_WAIT(n)  asm volatile("cp.async.wait_group %0;" :: "n"(n) : "memory")

__device__ __forceinline__ uint32_t f2tf32(float x) {
    uint32_t u;
    asm("cvt.rna.tf32.f32 %0, %1;" : "=r"(u) : "f"(x));
    return u;
}
__device__ __forceinline__ void tfsplit(float x, uint32_t& h, uint32_t& l) {
    h = f2tf32(x);
    l = f2tf32(x - __uint_as_float(h));   // residual subtraction is exact
}
__device__ __forceinline__ void mma_tf32(float* c, const uint32_t* a, uint32_t b0, uint32_t b1) {
    asm volatile("mma.sync.aligned.m16n8k8.row.col.f32.tf32.tf32.f32 "
        "{%0,%1,%2,%3}, {%4,%5,%6,%7}, {%8,%9}, {%0,%1,%2,%3};"
        : "+f"(c[0]), "+f"(c[1]), "+f"(c[2]), "+f"(c[3])
        : "r"(a[0]), "r"(a[1]), "r"(a[2]), "r"(a[3]), "r"(b0), "r"(b1));
}
// streaming (evict-first) float4 store: output bytes are never re-read
__device__ __forceinline__ void st_cs4(float* p, float a, float b, float c, float d) {
    asm volatile("st.global.cs.v4.f32 [%0], {%1,%2,%3,%4};"
                 :: "l"(p), "f"(a), "f"(b), "f"(c), "f"(d) : "memory");
}

// ---------------- W pre-split (tf32 hi/lo) ----------------
__global__ void conv_w_kernel(const float* __restrict__ W) {
    int i = blockIdx.x * 256 + threadIdx.x;
    uint32_t h, l;
    tfsplit(W[i], h, l);
    g_Whf[i] = __uint_as_float(h);
    g_Wlf[i] = __uint_as_float(l);
}

// ---------------- main fused kernel ----------------
__global__ __launch_bounds__(NTHR, 2)
void moe_gate_mma(const float* __restrict__ r, const float* __restrict__ W,
                  const float* __restrict__ bias,
                  float* __restrict__ out, size_t soft_base)
{
    extern __shared__ char smem[];
    const int tid  = threadIdx.x;
    const int warp = tid >> 5, lane = tid & 31;
    const int g    = lane >> 2, tg = lane & 3;
    const int row0 = blockIdx.x * TILE_M;

    if (tid < NEXP) *(float*)(smem + BIAS_OFF + tid * 4) = bias[tid];

    // ---- cp.async issue for one chunk into stage ci%3
    auto issue = [&](int ci) {
        const int s  = ci % 3;
        const int k0 = ci * KC;
#pragma unroll
        for (int i = 0; i < 8; i++) {                 // A: 128 rows x 8 x 16B
            int id = tid + i * NTHR;
            int row = id >> 3, seg = id & 7;
            cpa16(smem + A_OFF + s * A_STG + row * 144 + seg * 16,
                  r + (size_t)(row0 + row) * D_DIM + k0 + seg * 4);
        }
#pragma unroll
        for (int i = 0; i < 4; i++) {                 // B hi/lo: 64 rows x 8 x 16B each
            int id = tid + i * NTHR;
            int e = id >> 3, seg = id & 7;
            cpa16(smem + BH_OFF + s * B_STG + e * 144 + seg * 16,
                  g_Whf + (size_t)e * D_DIM + k0 + seg * 4);
            cpa16(smem + BL_OFF + s * B_STG + e * 144 + seg * 16,
                  g_Wlf + (size_t)e * D_DIM + k0 + seg * 4);
        }
        CP_COMMIT();
    };

    issue(0);
    issue(1);

    float c[2][8][4];
#pragma unroll
    for (int mt = 0; mt < 2; mt++)
#pragma unroll
        for (int nt = 0; nt < 8; nt++)
#pragma unroll
            for (int j = 0; j < 4; j++) c[mt][nt][j] = 0.f;

    for (int ci = 0; ci < NCH; ci++) {
        const int s = ci % 3;
        if (ci == NCH - 1) { CP_WAIT(0); } else { CP_WAIT(1); }
        __syncthreads();   // chunk ci landed; all warps done reading stage (ci+2)%3

        if (ci + 2 < NCH) issue(ci + 2);

        const char* As = smem + A_OFF + s * A_STG;
        const char* Bh = smem + BH_OFF + s * B_STG;
        const char* Bl = smem + BL_OFF + s * B_STG;

#pragma unroll
        for (int ks = 0; ks < 4; ks++) {
            // ---- A frags: load fp32, split to tf32 hi/lo in registers
            uint32_t ahi[2][4], alo[2][4];
#pragma unroll
            for (int mt = 0; mt < 2; mt++) {
                const float* ap = (const float*)(As + (warp * 32 + mt * 16 + g) * 144)
                                  + ks * 8 + tg;
                float a0 = ap[0];
                float a1 = ap[8 * 36];
                float a2 = ap[4];
                float a3 = ap[8 * 36 + 4];
                tfsplit(a0, ahi[mt][0], alo[mt][0]);
                tfsplit(a1, ahi[mt][1], alo[mt][1]);
                tfsplit(a2, ahi[mt][2], alo[mt][2]);
                tfsplit(a3, ahi[mt][3], alo[mt][3]);
            }
#pragma unroll
            for (int nt = 0; nt < 8; nt++) {
                const uint32_t* bhp = (const uint32_t*)(Bh + (nt * 8 + g) * 144) + ks * 8 + tg;
                const uint32_t* blp = (const uint32_t*)(Bl + (nt * 8 + g) * 144) + ks * 8 + tg;
                uint32_t bh0 = bhp[0], bh1 = bhp[4];
                uint32_t bl0 = blp[0], bl1 = blp[4];
#pragma unroll
                for (int mt = 0; mt < 2; mt++) {
                    mma_tf32(c[mt][nt], ahi[mt], bh0, bh1);   // hi*hi
                    mma_tf32(c[mt][nt], ahi[mt], bl0, bl1);   // hi*lo
                    mma_tf32(c[mt][nt], alo[mt], bh0, bh1);   // lo*hi
                }
            }
        }
    }
    __syncthreads();   // all MMAs done; smem A region free for logits staging

    // ---- scatter C frags to per-warp logits[32][LG_PAD]
    float* lg = (float*)(smem + warp * (32 * LG_PAD * 4));
#pragma unroll
    for (int mt = 0; mt < 2; mt++)
#pragma unroll
        for (int nt = 0; nt < 8; nt++) {
            int rr = mt * 16 + g, cc = nt * 8 + tg * 2;
            *(float2*)&lg[rr * LG_PAD + cc]       = make_float2(c[mt][nt][0], c[mt][nt][1]);
            *(float2*)&lg[(rr + 8) * LG_PAD + cc] = make_float2(c[mt][nt][2], c[mt][nt][3]);
        }
    __syncwarp();

    // ---- per-row softmax + top-8 (lane = row within warp)
    const float* bs = (const float*)(smem + BIAS_OFF);
    const int myrow = row0 + warp * 32 + lane;
    float v[64];
#pragma unroll
    for (int cc = 0; cc < NEXP; cc++) v[cc] = lg[lane * LG_PAD + cc] + bs[cc];

    float mx = -3.4e38f;
#pragma unroll
    for (int cc = 0; cc < NEXP; cc++) mx = fmaxf(mx, v[cc]);
    float ssum = 0.f;
#pragma unroll
    for (int cc = 0; cc < NEXP; cc++) ssum += __expf(v[cc] - mx);

    // top-9 sorted insert (8th + 9th for the margin test)
    float t[9];
#pragma unroll
    for (int j = 0; j < 9; j++) t[j] = -3.4e38f;
#pragma unroll
    for (int cc = 0; cc < NEXP; cc++) {
        float x = v[cc];
#pragma unroll
        for (int j = 0; j < 9; j++) {
            float hi = fmaxf(t[j], x), lo = fminf(t[j], x);
            t[j] = hi; x = lo;
        }
    }
    float thr = t[7];
    unsigned long long msk = 0ull;

    if (thr - t[8] >= MARGIN) {
        // ---- unambiguous: noisy selection is provably correct
        int cnt_gt = 0;
#pragma unroll
        for (int cc = 0; cc < NEXP; cc++) cnt_gt += (v[cc] > thr) ? 1 : 0;
        int quota = 8 - cnt_gt, eq = 0;
#pragma unroll
        for (int cc = 0; cc < NEXP; cc++) {
            bool sg = v[cc] > thr;
            bool se = (v[cc] == thr) && (eq < quota);
            if (se) eq++;
            if (sg || se) msk |= 1ull << cc;
        }
    } else {
        // ---- ambiguous boundary (~0.5% of rows): exact fp32 recompute
        int   cidx[MAXC];
        float cval[MAXC];
        int nc = 0;
        float lim = thr - MARGIN;
        for (int cc = 0; cc < NEXP; cc++)
            if (v[cc] >= lim && nc < MAXC) { cidx[nc++] = cc; }

        const float* rrow = r + (size_t)myrow * D_DIM;
        for (int j = 0; j < nc; j++) {
            const float* wrow = W + (size_t)cidx[j] * D_DIM;
            float s0 = 0.f, s1 = 0.f, s2 = 0.f, s3 = 0.f;
            for (int k = 0; k < D_DIM; k += 4) {
                float4 a = *(const float4*)(rrow + k);
                float4 w = *(const float4*)(wrow + k);
                s0 = fmaf(a.x, w.x, s0); s1 = fmaf(a.y, w.y, s1);
                s2 = fmaf(a.z, w.z, s2); s3 = fmaf(a.w, w.w, s3);
            }
            cval[j] = (s0 + s1) + (s2 + s3) + bs[cidx[j]];
        }
        for (int it = 0; it < 8; it++) {
            float best = -3.4e38f; int bj = 0;
            for (int j = 0; j < nc; j++) {
                bool freej = ((msk >> cidx[j]) & 1ull) == 0ull;
                if (freej && cval[j] > best) { best = cval[j]; bj = j; }
            }
            msk |= 1ull << cidx[bj];
        }
    }

    float selexp = 0.f;
#pragma unroll
    for (int cc = 0; cc < NEXP; cc++)
        if ((msk >> cc) & 1ull) selexp += __expf(v[cc] - mx);

    float inv_s = 1.0f / ssum;
    float inv_d = 1.0f / (selexp * inv_s + 1e-9f);

    const size_t gr = (size_t)myrow * NEXP;
#pragma unroll
    for (int c4 = 0; c4 < NEXP; c4 += 4) {
        float sf[4], hd[4];
#pragma unroll
        for (int j = 0; j < 4; j++) {
            float soft = __expf(v[c4 + j] - mx) * inv_s;
            sf[j] = soft;
            hd[j] = ((msk >> (c4 + j)) & 1ull) ? soft * inv_d : 0.f;
        }
        st_cs4(out + gr + c4,             hd[0], hd[1], hd[2], hd[3]);
        st_cs4(out + soft_base + gr + c4, sf[0], sf[1], sf[2], sf[3]);
    }
}

extern "C" void kernel_launch(void* const* d_in, const int* in_sizes, int n_in,
                              void* d_out, int out_size)
{
    const float* r = (const float*)d_in[0];   // (B, 2048) fp32
    const float* W = (const float*)d_in[1];   // (64, 2048) fp32
    const float* b = (const float*)d_in[2];   // (64,) fp32
    float* out = (float*)d_out;               // [hard | soft]

    int B = in_sizes[0] / D_DIM;              // 32768
    size_t soft_base = (size_t)out_size / 2;

    cudaFuncSetAttribute(moe_gate_mma, cudaFuncAttributeMaxDynamicSharedMemorySize, SMEM_TOTAL);

    conv_w_kernel<<<(NEXP * D_DIM) / 256, 256>>>(W);
    moe_gate_mma<<<B / TILE_M, NTHR, SMEM_TOTAL>>>(r, W, b, out, soft_base);
}

// round 17
// speedup vs baseline: 2.5951x; 1.0229x over previous
#include <cuda_runtime.h>
#include <cstdint>
#include <cstddef>

#define D_DIM  2048
#define NEXP   64
#define TILE_M 128
#define KC     32
#define NCH    (D_DIM / KC)   // 64 chunks
#define NTHR   128
#define MARGIN 2e-4f
#define MAXC   16

// ---- smem layout (bytes). Row stride 144B = 36 floats -> conflict-free frags.
#define A_OFF    0             // 3 stages x 128 rows x 144B
#define A_STG    18432
#define B_OFF    55296         // 3 stages x 64 rows x 144B (raw fp32 W)
#define B_STG    9216
#define BIAS_OFF 82944
#define SMEM_TOTAL 83200
#define LG_PAD   66            // epilogue logits row pad (floats)

// ---------------- helpers ----------------
__device__ __forceinline__ uint32_t smem_u32(const void* p) {
    uint32_t a;
    asm("{ .reg .u64 t; cvta.to.shared.u64 t, %1; cvt.u32.u64 %0, t; }" : "=r"(a) : "l"(p));
    return a;
}
__device__ __forceinline__ void cpa16(void* dst, const void* src) {
    asm volatile("cp.async.cg.shared.global [%0], [%1], 16;"
                 :: "r"(smem_u32(dst)), "l"(src) : "memory");
}
#define CP_COMMIT() asm volatile("cp.async.commit_group;" ::: "memory")
#define CP_WAIT(n)  asm volatile("cp.async.wait_group %0;" :: "n"(n) : "memory")

__device__ __forceinline__ uint32_t f2tf32(float x) {
    uint32_t u;
    asm("cvt.rna.tf32.f32 %0, %1;" : "=r"(u) : "f"(x));
    return u;
}
__device__ __forceinline__ void tfsplit(float x, uint32_t& h, uint32_t& l) {
    h = f2tf32(x);
    l = f2tf32(x - __uint_as_float(h));   // residual subtraction is exact
}
__device__ __forceinline__ void mma_tf32(float* c, const uint32_t* a, uint32_t b0, uint32_t b1) {
    asm volatile("mma.sync.aligned.m16n8k8.row.col.f32.tf32.tf32.f32 "
        "{%0,%1,%2,%3}, {%4,%5,%6,%7}, {%8,%9}, {%0,%1,%2,%3};"
        : "+f"(c[0]), "+f"(c[1]), "+f"(c[2]), "+f"(c[3])
        : "r"(a[0]), "r"(a[1]), "r"(a[2]), "r"(a[3]), "r"(b0), "r"(b1));
}
// streaming (evict-first) float4 store: output bytes are never re-read
__device__ __forceinline__ void st_cs4(float* p, float a, float b, float c, float d) {
    asm volatile("st.global.cs.v4.f32 [%0], {%1,%2,%3,%4};"
                 :: "l"(p), "f"(a), "f"(b), "f"(c), "f"(d) : "memory");
}

// ---------------- main fused kernel (no prelude kernel) ----------------
__global__ __launch_bounds__(NTHR, 2)
void moe_gate_mma(const float* __restrict__ r, const float* __restrict__ W,
                  const float* __restrict__ bias,
                  float* __restrict__ out, size_t soft_base)
{
    extern __shared__ char smem[];
    const int tid  = threadIdx.x;
    const int warp = tid >> 5, lane = tid & 31;
    const int g    = lane >> 2, tg = lane & 3;
    const int row0 = blockIdx.x * TILE_M;

    if (tid < NEXP) *(float*)(smem + BIAS_OFF + tid * 4) = bias[tid];

    // ---- cp.async issue for one chunk into stage ci%3 (A fp32 + raw W fp32)
    auto issue = [&](int ci) {
        const int s  = ci % 3;
        const int k0 = ci * KC;
#pragma unroll
        for (int i = 0; i < 8; i++) {                 // A: 128 rows x 8 x 16B
            int id = tid + i * NTHR;
            int row = id >> 3, seg = id & 7;
            cpa16(smem + A_OFF + s * A_STG + row * 144 + seg * 16,
                  r + (size_t)(row0 + row) * D_DIM + k0 + seg * 4);
        }
#pragma unroll
        for (int i = 0; i < 4; i++) {                 // B raw: 64 rows x 8 x 16B
            int id = tid + i * NTHR;
            int e = id >> 3, seg = id & 7;
            cpa16(smem + B_OFF + s * B_STG + e * 144 + seg * 16,
                  W + (size_t)e * D_DIM + k0 + seg * 4);
        }
        CP_COMMIT();
    };

    issue(0);
    issue(1);

    float c[2][8][4];
#pragma unroll
    for (int mt = 0; mt < 2; mt++)
#pragma unroll
        for (int nt = 0; nt < 8; nt++)
#pragma unroll
            for (int j = 0; j < 4; j++) c[mt][nt][j] = 0.f;

    for (int ci = 0; ci < NCH; ci++) {
        const int s = ci % 3;
        if (ci == NCH - 1) { CP_WAIT(0); } else { CP_WAIT(1); }
        __syncthreads();   // chunk ci landed; all warps done reading stage (ci+2)%3

        if (ci + 2 < NCH) issue(ci + 2);

        const char* As = smem + A_OFF + s * A_STG;
        const char* Bs = smem + B_OFF + s * B_STG;

#pragma unroll
        for (int ks = 0; ks < 4; ks++) {
            // ---- A frags: load fp32, split to tf32 hi/lo in registers
            uint32_t ahi[2][4], alo[2][4];
#pragma unroll
            for (int mt = 0; mt < 2; mt++) {
                const float* ap = (const float*)(As + (warp * 32 + mt * 16 + g) * 144)
                                  + ks * 8 + tg;
                float a0 = ap[0];
                float a1 = ap[8 * 36];
                float a2 = ap[4];
                float a3 = ap[8 * 36 + 4];
                tfsplit(a0, ahi[mt][0], alo[mt][0]);
                tfsplit(a1, ahi[mt][1], alo[mt][1]);
                tfsplit(a2, ahi[mt][2], alo[mt][2]);
                tfsplit(a3, ahi[mt][3], alo[mt][3]);
            }
#pragma unroll
            for (int nt = 0; nt < 8; nt++) {
                // ---- B frags: raw fp32 -> tf32 hi/lo in registers (bit-identical
                //      to the former precomputed g_Whf/g_Wlf values)
                const float* bp = (const float*)(Bs + (nt * 8 + g) * 144) + ks * 8 + tg;
                uint32_t bh0, bl0, bh1, bl1;
                tfsplit(bp[0], bh0, bl0);
                tfsplit(bp[4], bh1, bl1);
#pragma unroll
                for (int mt = 0; mt < 2; mt++) {
                    mma_tf32(c[mt][nt], ahi[mt], bh0, bh1);   // hi*hi
                    mma_tf32(c[mt][nt], ahi[mt], bl0, bl1);   // hi*lo
                    mma_tf32(c[mt][nt], alo[mt], bh0, bh1);   // lo*hi
                }
            }
        }
    }
    __syncthreads();   // all MMAs done; smem A region free for logits staging

    // ---- scatter C frags to per-warp logits[32][LG_PAD]
    float* lg = (float*)(smem + warp * (32 * LG_PAD * 4));
#pragma unroll
    for (int mt = 0; mt < 2; mt++)
#pragma unroll
        for (int nt = 0; nt < 8; nt++) {
            int rr = mt * 16 + g, cc = nt * 8 + tg * 2;
            *(float2*)&lg[rr * LG_PAD + cc]       = make_float2(c[mt][nt][0], c[mt][nt][1]);
            *(float2*)&lg[(rr + 8) * LG_PAD + cc] = make_float2(c[mt][nt][2], c[mt][nt][3]);
        }
    __syncwarp();

    // ---- per-row softmax + top-8 (lane = row within warp)
    const float* bs = (const float*)(smem + BIAS_OFF);
    const int myrow = row0 + warp * 32 + lane;
    float v[64];
#pragma unroll
    for (int cc = 0; cc < NEXP; cc++) v[cc] = lg[lane * LG_PAD + cc] + bs[cc];

    float mx = -3.4e38f;
#pragma unroll
    for (int cc = 0; cc < NEXP; cc++) mx = fmaxf(mx, v[cc]);
    float ssum = 0.f;
#pragma unroll
    for (int cc = 0; cc < NEXP; cc++) ssum += __expf(v[cc] - mx);

    // top-9 sorted insert (8th + 9th for the margin test)
    float t[9];
#pragma unroll
    for (int j = 0; j < 9; j++) t[j] = -3.4e38f;
#pragma unroll
    for (int cc = 0; cc < NEXP; cc++) {
        float x = v[cc];
#pragma unroll
        for (int j = 0; j < 9; j++) {
            float hi = fmaxf(t[j], x), lo = fminf(t[j], x);
            t[j] = hi; x = lo;
        }
    }
    float thr = t[7];
    unsigned long long msk = 0ull;

    if (thr - t[8] >= MARGIN) {
        // ---- unambiguous: noisy selection is provably correct
        int cnt_gt = 0;
#pragma unroll
        for (int cc = 0; cc < NEXP; cc++) cnt_gt += (v[cc] > thr) ? 1 : 0;
        int quota = 8 - cnt_gt, eq = 0;
#pragma unroll
        for (int cc = 0; cc < NEXP; cc++) {
            bool sg = v[cc] > thr;
            bool se = (v[cc] == thr) && (eq < quota);
            if (se) eq++;
            if (sg || se) msk |= 1ull << cc;
        }
    } else {
        // ---- ambiguous boundary (~0.5% of rows): exact fp32 recompute
        int   cidx[MAXC];
        float cval[MAXC];
        int nc = 0;
        float lim = thr - MARGIN;
        for (int cc = 0; cc < NEXP; cc++)
            if (v[cc] >= lim && nc < MAXC) { cidx[nc++] = cc; }

        const float* rrow = r + (size_t)myrow * D_DIM;
        for (int j = 0; j < nc; j++) {
            const float* wrow = W + (size_t)cidx[j] * D_DIM;
            float s0 = 0.f, s1 = 0.f, s2 = 0.f, s3 = 0.f;
            for (int k = 0; k < D_DIM; k += 4) {
                float4 a = *(const float4*)(rrow + k);
                float4 w = *(const float4*)(wrow + k);
                s0 = fmaf(a.x, w.x, s0); s1 = fmaf(a.y, w.y, s1);
                s2 = fmaf(a.z, w.z, s2); s3 = fmaf(a.w, w.w, s3);
            }
            cval[j] = (s0 + s1) + (s2 + s3) + bs[cidx[j]];
        }
        for (int it = 0; it < 8; it++) {
            float best = -3.4e38f; int bj = 0;
            for (int j = 0; j < nc; j++) {
                bool freej = ((msk >> cidx[j]) & 1ull) == 0ull;
                if (freej && cval[j] > best) { best = cval[j]; bj = j; }
            }
            msk |= 1ull << cidx[bj];
        }
    }

    float selexp = 0.f;
#pragma unroll
    for (int cc = 0; cc < NEXP; cc++)
        if ((msk >> cc) & 1ull) selexp += __expf(v[cc] - mx);

    float inv_s = 1.0f / ssum;
    float inv_d = 1.0f / (selexp * inv_s + 1e-9f);

    const size_t gr = (size_t)myrow * NEXP;
#pragma unroll
    for (int c4 = 0; c4 < NEXP; c4 += 4) {
        float sf[4], hd[4];
#pragma unroll
        for (int j = 0; j < 4; j++) {
            float soft = __expf(v[c4 + j] - mx) * inv_s;
            sf[j] = soft;
            hd[j] = ((msk >> (c4 + j)) & 1ull) ? soft * inv_d : 0.f;
        }
        st_cs4(out + gr + c4,             hd[0], hd[1], hd[2], hd[3]);
        st_cs4(out + soft_base + gr + c4, sf[0], sf[1], sf[2], sf[3]);
    }
}

extern "C" void kernel_launch(void* const* d_in, const int* in_sizes, int n_in,
                              void* d_out, int out_size)
{
    const float* r = (const float*)d_in[0];   // (B, 2048) fp32
    const float* W = (const float*)d_in[1];   // (64, 2048) fp32
    const float* b = (const float*)d_in[2];   // (64,) fp32
    float* out = (float*)d_out;               // [hard | soft]

    int B = in_sizes[0] / D_DIM;              // 32768
    size_t soft_base = (size_t)out_size / 2;

    cudaFuncSetAttribute(moe_gate_mma, cudaFuncAttributeMaxDynamicSharedMemorySize, SMEM_TOTAL);

    moe_gate_mma<<<B / TILE_M, NTHR, SMEM_TOTAL>>>(r, W, b, out, soft_base);
}